// round 7
// baseline (speedup 1.0000x reference)
#include <cuda_runtime.h>
#include <cstdint>

#define B_   4
#define H_   16
#define T_   2048
#define C_   1024
#define D_   64
#define BH_  64

__device__ float g_q[BH_*T_*D_];
__device__ float g_k[BH_*T_*D_];
__device__ float g_v[BH_*T_*D_];
__device__ float g_att[BH_*T_*D_];
__device__ float g_invZ[BH_*T_];

__device__ __forceinline__ float to_tf32(float f){
    uint32_t r; asm("cvt.rna.tf32.f32 %0, %1;" : "=r"(r) : "f"(f));
    return __uint_as_float(r);
}

__device__ __forceinline__ void mma8(float4 &c, const uint32_t* a, const uint32_t* b){
    asm volatile("mma.sync.aligned.m16n8k8.row.col.f32.tf32.tf32.f32 "
        "{%0,%1,%2,%3}, {%4,%5,%6,%7}, {%8,%9}, {%0,%1,%2,%3};"
        : "+f"(c.x), "+f"(c.y), "+f"(c.z), "+f"(c.w)
        : "r"(a[0]), "r"(a[1]), "r"(a[2]), "r"(a[3]), "r"(b[0]), "r"(b[1]));
}

// ---------------- fragment-major smem layouts ----------------
// A-frag: [mb(16 rows)][ks(8 k)][lane][4 regs]; lane=(m&7)*4+(k&3), reg=((m>>3)&1)+2*((k>>2)&1)
// B-frag: [nb(8 cols)][ks(8 k)][lane][2 regs]; lane=(n&7)*4+(k&3), reg=(k>>2)&1

__device__ __forceinline__ void stA_k4(float* Af, int KS, int m, int k, float4 v){
    int base = (((m>>4)*KS + (k>>3))*32 + ((m&7)*4))*4 + ((m>>3)&1) + 2*((k>>2)&1);
    Af[base]    = to_tf32(v.x);
    Af[base+4]  = to_tf32(v.y);
    Af[base+8]  = to_tf32(v.z);
    Af[base+12] = to_tf32(v.w);
}
__device__ __forceinline__ void stB_n4(float* Bf, int KS, int k, int n, float4 v){
    int base = (((n>>3)*KS + (k>>3))*32 + ((n&7)*4 + (k&3)))*2 + ((k>>2)&1);
    Bf[base]    = to_tf32(v.x);
    Bf[base+8]  = to_tf32(v.y);
    Bf[base+16] = to_tf32(v.z);
    Bf[base+24] = to_tf32(v.w);
}
__device__ __forceinline__ void stB_k4(float* Bf, int KS, int n, int k, float4 v){
    int base = (((n>>3)*KS + (k>>3))*32 + ((n&7)*4))*2 + ((k>>2)&1);
    Bf[base]   = to_tf32(v.x);
    Bf[base+2] = to_tf32(v.y);
    Bf[base+4] = to_tf32(v.z);
    Bf[base+6] = to_tf32(v.w);
}
__device__ __forceinline__ void stP1(float* Pf, int KS, int q, int s, float v){
    Pf[(((q>>4)*KS + (s>>3))*32 + ((q&7)*4 + (s&3)))*4 + ((q>>3)&1) + 2*((s>>2)&1)] = to_tf32(v);
}

#define LDA4(Af, KS, mb, ks, lane) (*(const uint4*)((Af) + ((((mb)*(KS))+(ks))*32 + (lane))*4))
#define LDB2(Bf, KS, nb, ks, lane) (*(const uint2*)((Bf) + ((((nb)*(KS))+(ks))*32 + (lane))*2))

// =====================================================================
// K1: QKV projection. Block 256(m) x 64(n), 4 warps of 64x64, k-chunk 32.
// Static smem 40KB.
// =====================================================================
__global__ __launch_bounds__(128) void qkv_kernel(
    const float* __restrict__ x, const float* __restrict__ Wq,
    const float* __restrict__ Wk, const float* __restrict__ Wv)
{
    __shared__ float Af[16*4*128];   // 32KB
    __shared__ float Bf[8*4*64];     // 8KB
    int tid=threadIdx.x, lane=tid&31, w=tid>>5;
    int g=lane>>2, tg=lane&3;
    int bh=blockIdx.y, b=bh>>4, h=bh&15;
    int m0=blockIdx.x*256;
    const float* W = (blockIdx.z==0?Wq:(blockIdx.z==1?Wk:Wv)) + (size_t)h*C_*D_;
    float* out = (blockIdx.z==0?g_q:(blockIdx.z==1?g_k:g_v)) + ((size_t)bh*T_+m0)*D_;
    const float* A = x + ((size_t)b*T_+m0)*C_;

    float4 c[4][8];
    #pragma unroll
    for(int i=0;i<4;i++)
        #pragma unroll
        for(int j=0;j<8;j++) c[i][j]=make_float4(0.f,0.f,0.f,0.f);

    for(int k0=0;k0<C_;k0+=32){
        __syncthreads();
        #pragma unroll
        for(int i=0;i<16;i++){
            int idx=tid+i*128, m=idx>>3, kq=(idx&7)*4;
            stA_k4(Af, 4, m, kq, *(const float4*)(A+(size_t)m*C_+k0+kq));
        }
        #pragma unroll
        for(int i=0;i<4;i++){
            int idx=tid+i*128, r=idx>>4, nq=(idx&15)*4;
            stB_n4(Bf, 4, r, nq, *(const float4*)(W+(size_t)(k0+r)*D_+nq));
        }
        __syncthreads();
        #pragma unroll
        for(int ks=0;ks<4;ks++){
            uint4 a[4]; uint2 bb[8];
            #pragma unroll
            for(int i=0;i<4;i++) a[i]=LDA4(Af, 4, w*4+i, ks, lane);
            #pragma unroll
            for(int j=0;j<8;j++) bb[j]=LDB2(Bf, 4, j, ks, lane);
            #pragma unroll
            for(int i=0;i<4;i++)
                #pragma unroll
                for(int j=0;j<8;j++) mma8(c[i][j], (const uint32_t*)&a[i], (const uint32_t*)&bb[j]);
        }
    }
    #pragma unroll
    for(int i=0;i<4;i++){
        int m=w*64+i*16+g;
        #pragma unroll
        for(int j=0;j<8;j++){
            int n=j*8+2*tg;
            *(float2*)(out+(size_t)m*D_+n)     = make_float2(c[i][j].x, c[i][j].y);
            *(float2*)(out+(size_t)(m+8)*D_+n) = make_float2(c[i][j].z, c[i][j].w);
        }
    }
}

// =====================================================================
// K2: per-key Z via S^T = K.Q^T. Block: 64 keys x streamed 64-query tiles.
// 4 warps of 64(s) x 16(t). Static smem 32.25KB.
// =====================================================================
__global__ __launch_bounds__(128) void colsum_kernel()
{
    __shared__ float Kf[4096];   // A-frag: 4 mb x 8 ks x 128
    __shared__ float Qf[4096];   // B-frag: 8 nb x 8 ks x 64
    __shared__ float zsh[64];
    int tid=threadIdx.x, lane=tid&31, w=tid>>5;
    int g=lane>>2, tg=lane&3;
    int bh=blockIdx.y, s0=blockIdx.x*64;
    const float* kb=g_k+(size_t)bh*T_*D_;
    const float* qb=g_q+(size_t)bh*T_*D_;

    if(tid<64) zsh[tid]=0.f;
    #pragma unroll
    for(int i=0;i<8;i++){
        int idx=tid+i*128, s=idx>>4, kq=(idx&15)*4;
        stA_k4(Kf, 8, s, kq, *(const float4*)(kb+(size_t)(s0+s)*D_+kq));
    }

    float zrow[4][2];
    #pragma unroll
    for(int i=0;i<4;i++){ zrow[i][0]=0.f; zrow[i][1]=0.f; }

    for(int t0=s0; t0<T_; t0+=64){
        __syncthreads();
        #pragma unroll
        for(int i=0;i<8;i++){
            int idx=tid+i*128, t=idx>>4, kq=(idx&15)*4;
            stB_k4(Qf, 8, t, kq, *(const float4*)(qb+(size_t)(t0+t)*D_+kq));
        }
        __syncthreads();

        float4 c[4][2];
        #pragma unroll
        for(int i=0;i<4;i++){ c[i][0]=make_float4(0.f,0.f,0.f,0.f); c[i][1]=make_float4(0.f,0.f,0.f,0.f); }
        #pragma unroll
        for(int ks=0;ks<8;ks++){
            uint4 a[4]; uint2 bb[2];
            #pragma unroll
            for(int i=0;i<4;i++) a[i]=LDA4(Kf, 8, i, ks, lane);
            #pragma unroll
            for(int j=0;j<2;j++) bb[j]=LDB2(Qf, 8, w*2+j, ks, lane);
            #pragma unroll
            for(int i=0;i<4;i++)
                #pragma unroll
                for(int j=0;j<2;j++) mma8(c[i][j], (const uint32_t*)&a[i], (const uint32_t*)&bb[j]);
        }
        #pragma unroll
        for(int i=0;i<4;i++){
            int sr0=s0+i*16+g, sr1=sr0+8;
            #pragma unroll
            for(int j=0;j<2;j++){
                int tc0=t0+w*16+j*8+2*tg, tc1=tc0+1;
                float4 S=c[i][j];
                zrow[i][0] += (tc0>=sr0)?__expf(S.x*0.125f):0.f;
                zrow[i][0] += (tc1>=sr0)?__expf(S.y*0.125f):0.f;
                zrow[i][1] += (tc0>=sr1)?__expf(S.z*0.125f):0.f;
                zrow[i][1] += (tc1>=sr1)?__expf(S.w*0.125f):0.f;
            }
        }
    }
    __syncthreads();
    #pragma unroll
    for(int i=0;i<4;i++)
        #pragma unroll
        for(int rr=0;rr<2;rr++){
            float v=zrow[i][rr];
            v += __shfl_xor_sync(0xffffffffu, v, 1);
            v += __shfl_xor_sync(0xffffffffu, v, 2);
            if(tg==0) atomicAdd(&zsh[i*16+g+rr*8], v);
        }
    __syncthreads();
    if(tid<64) g_invZ[(size_t)bh*T_+s0+tid]=1.0f/zsh[tid];
}

// =====================================================================
// K3: attention. Block 64 queries, 64-key tiles. 4 warps (2q x 2s / 2q x 2d).
// P aliases the K buffer (K dead after stage1). Static smem 48KB exactly.
// =====================================================================
__global__ __launch_bounds__(128) void attn_kernel()
{
    __shared__ float Qf [4096];   // A-frag Q: 4 mb x 8 ks x 128  (16KB)
    __shared__ float KPf[4096];   // B-frag K (stage1) / A-frag P (stage2) (16KB)
    __shared__ float Vf [4096];   // B-frag V: 8 nb x 8 ks x 64   (16KB)
    int tid=threadIdx.x, lane=tid&31, warp=tid>>5;
    int g=lane>>2, tg=lane&3;
    int wm=warp>>1, wn=warp&1;
    int bh=blockIdx.y;
    int t0=((int)gridDim.x-1-(int)blockIdx.x)*64;   // big tiles first
    const float* qb=g_q+(size_t)bh*T_*D_;
    const float* kb=g_k+(size_t)bh*T_*D_;
    const float* vb=g_v+(size_t)bh*T_*D_;
    const float* iz=g_invZ+(size_t)bh*T_;

    #pragma unroll
    for(int i=0;i<8;i++){
        int idx=tid+i*128, t=idx>>4, kq=(idx&15)*4;
        stA_k4(Qf, 8, t, kq, *(const float4*)(qb+(size_t)(t0+t)*D_+kq));
    }

    float4 oacc[2][4];
    #pragma unroll
    for(int i=0;i<2;i++)
        #pragma unroll
        for(int j=0;j<4;j++) oacc[i][j]=make_float4(0.f,0.f,0.f,0.f);

    for(int s0=0; s0<=t0; s0+=64){
        __syncthreads();   // prev stage2 readers of KPf/Vf done (covers Qf load on iter 0 w/ next sync)
        #pragma unroll
        for(int i=0;i<8;i++){
            int idx=tid+i*128, r=idx>>4, kq=(idx&15)*4;
            stB_k4(KPf, 8, r, kq, *(const float4*)(kb+(size_t)(s0+r)*D_+kq));
            stB_n4(Vf,  8, r, kq, *(const float4*)(vb+(size_t)(s0+r)*D_+kq));
        }
        __syncthreads();

        // stage1: S[64x64] = Q.K^T, warps 2q x 2s of 32x32
        float4 s1[2][4];
        #pragma unroll
        for(int i=0;i<2;i++)
            #pragma unroll
            for(int j=0;j<4;j++) s1[i][j]=make_float4(0.f,0.f,0.f,0.f);
        #pragma unroll
        for(int ks=0;ks<8;ks++){
            uint4 a[2]; uint2 bb[4];
            #pragma unroll
            for(int i=0;i<2;i++) a[i]=LDA4(Qf, 8, wm*2+i, ks, lane);
            #pragma unroll
            for(int j=0;j<4;j++) bb[j]=LDB2(KPf, 8, wn*4+j, ks, lane);
            #pragma unroll
            for(int i=0;i<2;i++)
                #pragma unroll
                for(int j=0;j<4;j++) mma8(s1[i][j], (const uint32_t*)&a[i], (const uint32_t*)&bb[j]);
        }
        __syncthreads();   // all stage1 reads of K done before P overwrites KPf

        float izv0[4], izv1[4];
        #pragma unroll
        for(int j=0;j<4;j++){
            int sl0=wn*32+j*8+2*tg;
            izv0[j]=__ldg(iz+s0+sl0);
            izv1[j]=__ldg(iz+s0+sl0+1);
        }
        #pragma unroll
        for(int i=0;i<2;i++){
            int ql0=wm*32+i*16+g;
            int qg0=t0+ql0, qg1=qg0+8;
            #pragma unroll
            for(int j=0;j<4;j++){
                int sl0=wn*32+j*8+2*tg, sl1=sl0+1;
                int sg0=s0+sl0, sg1=sg0+1;
                float4 S=s1[i][j];
                float w00=(qg0>=sg0)?__expf(S.x*0.125f)*izv0[j]:0.f;
                float w01=(qg0>=sg1)?__expf(S.y*0.125f)*izv1[j]:0.f;
                float w10=(qg1>=sg0)?__expf(S.z*0.125f)*izv0[j]:0.f;
                float w11=(qg1>=sg1)?__expf(S.w*0.125f)*izv1[j]:0.f;
                stP1(KPf, 8, ql0,   sl0, w00);
                stP1(KPf, 8, ql0,   sl1, w01);
                stP1(KPf, 8, ql0+8, sl0, w10);
                stP1(KPf, 8, ql0+8, sl1, w11);
            }
        }
        __syncthreads();

        // stage2: O[64x64] += P.V, warps 2q x 2d of 32x32
        #pragma unroll
        for(int ks=0;ks<8;ks++){
            uint4 a[2]; uint2 bb[4];
            #pragma unroll
            for(int i=0;i<2;i++) a[i]=LDA4(KPf, 8, wm*2+i, ks, lane);
            #pragma unroll
            for(int j=0;j<4;j++) bb[j]=LDB2(Vf, 8, wn*4+j, ks, lane);
            #pragma unroll
            for(int i=0;i<2;i++)
                #pragma unroll
                for(int j=0;j<4;j++) mma8(oacc[i][j], (const uint32_t*)&a[i], (const uint32_t*)&bb[j]);
        }
    }

    float* ob=g_att+((size_t)bh*T_+t0)*D_;
    #pragma unroll
    for(int i=0;i<2;i++){
        int q=wm*32+i*16+g;
        #pragma unroll
        for(int j=0;j<4;j++){
            int d=wn*32+j*8+2*tg;
            *(float2*)(ob+(size_t)q*D_+d)     = make_float2(oacc[i][j].x, oacc[i][j].y);
            *(float2*)(ob+(size_t)(q+8)*D_+d) = make_float2(oacc[i][j].z, oacc[i][j].w);
        }
    }
}

// =====================================================================
// K4: output projection + bias. Block 128(m) x 128(n), 4 warps of 64x64,
// k-chunk 32. Static smem 32KB.
// =====================================================================
__global__ __launch_bounds__(128) void oproj_kernel(
    const float* __restrict__ Wo, const float* __restrict__ bo, float* __restrict__ out)
{
    __shared__ float Af[8*4*128];   // 16KB
    __shared__ float Bf[16*4*64];   // 16KB
    int tid=threadIdx.x, lane=tid&31, warp=tid>>5;
    int g=lane>>2, tg=lane&3;
    int wm=warp&1, wn=warp>>1;
    int m0=blockIdx.x*128, n0=blockIdx.y*128;

    float4 c[4][8];
    #pragma unroll
    for(int i=0;i<4;i++)
        #pragma unroll
        for(int j=0;j<8;j++) c[i][j]=make_float4(0.f,0.f,0.f,0.f);

    for(int k0=0;k0<C_;k0+=32){
        __syncthreads();
        #pragma unroll
        for(int i=0;i<8;i++){
            int idx=tid+i*128, m=idx>>3, kq=(idx&7)*4;
            int mg=m0+m, b=mg>>11, t=mg&2047;
            int k=k0+kq, hk=k>>6, dk=k&63;
            stA_k4(Af, 4, m, kq, *(const float4*)(g_att+(((size_t)(b*H_+hk))*T_+t)*D_+dk));
        }
        #pragma unroll
        for(int i=0;i<8;i++){
            int idx=tid+i*128, r=idx>>5, nq=(idx&31)*4;
            stB_n4(Bf, 4, r, nq, *(const float4*)(Wo+(size_t)(k0+r)*C_+n0+nq));
        }
        __syncthreads();
        #pragma unroll
        for(int ks=0;ks<4;ks++){
            uint4 a[4]; uint2 bb[8];
            #pragma unroll
            for(int i=0;i<4;i++) a[i]=LDA4(Af, 4, wm*4+i, ks, lane);
            #pragma unroll
            for(int j=0;j<8;j++) bb[j]=LDB2(Bf, 4, wn*8+j, ks, lane);
            #pragma unroll
            for(int i=0;i<4;i++)
                #pragma unroll
                for(int j=0;j<8;j++) mma8(c[i][j], (const uint32_t*)&a[i], (const uint32_t*)&bb[j]);
        }
    }
    #pragma unroll
    for(int i=0;i<4;i++){
        int m=m0+wm*64+i*16+g;
        #pragma unroll
        for(int j=0;j<8;j++){
            int n=n0+wn*64+j*8+2*tg;
            float b0v=bo[n], b1v=bo[n+1];
            *(float2*)(out+(size_t)m*C_+n)     = make_float2(c[i][j].x+b0v, c[i][j].y+b1v);
            *(float2*)(out+(size_t)(m+8)*C_+n) = make_float2(c[i][j].z+b0v, c[i][j].w+b1v);
        }
    }
}

// =====================================================================
extern "C" void kernel_launch(void* const* d_in, const int* in_sizes, int n_in,
                              void* d_out, int out_size)
{
    const float* x  = (const float*)d_in[0];
    const float* Wq = (const float*)d_in[1];
    const float* Wk = (const float*)d_in[2];
    const float* Wv = (const float*)d_in[3];
    const float* Wo = (const float*)d_in[4];
    const float* bo = (const float*)d_in[5];
    float* out = (float*)d_out;

    qkv_kernel   <<<dim3(T_/256, BH_, 3), 128>>>(x, Wq, Wk, Wv);
    colsum_kernel<<<dim3(T_/64,  BH_),    128>>>();
    attn_kernel  <<<dim3(T_/64,  BH_),    128>>>();
    oproj_kernel <<<dim3((B_*T_)/128, C_/128), 128>>>(Wo, bo, out);
}